// round 1
// baseline (speedup 1.0000x reference)
#include <cuda_runtime.h>

// Problem constants (shapes are fixed by the dataset).
#define NE_MAX 100000
#define NR_MAX 1000

// Scratch: per-entity state vectors (16 complex) and per-relation 16x16 matrices.
__device__ float2 g_ve[NE_MAX * 16];   // 12.8 MB
__device__ float2 g_mr[NR_MAX * 256];  // 2.0 MB, row-major M[r][i][j]

// ---------------------------------------------------------------------------
// Gate math
// ---------------------------------------------------------------------------
// PennyLane Rot(phi, theta, omega) matrix:
//   m00 = e^{-i(phi+omega)/2} cos(th/2)
//   m01 = -e^{+i(phi-omega)/2} sin(th/2)
//   m10 =  e^{-i(phi-omega)/2} sin(th/2)
//   m11 =  e^{+i(phi+omega)/2} cos(th/2)
__device__ __forceinline__ void rot_mat(float phi, float th, float om,
                                        float2& m00, float2& m01,
                                        float2& m10, float2& m11) {
    float st, ct, sa, ca, sb, cb;
    sincosf(0.5f * th, &st, &ct);
    sincosf(0.5f * (phi + om), &sa, &ca);
    sincosf(0.5f * (phi - om), &sb, &cb);
    m00 = make_float2(ca * ct, -sa * ct);
    m01 = make_float2(-cb * st, -sb * st);
    m10 = make_float2(cb * st, -sb * st);
    m11 = make_float2(ca * ct, sa * ct);
}

__device__ __forceinline__ void gate_pair(float2& a, float2& b,
                                          float2 m00, float2 m01,
                                          float2 m10, float2 m11) {
    float2 na, nb;
    na.x = m00.x * a.x - m00.y * a.y + m01.x * b.x - m01.y * b.y;
    na.y = m00.x * a.y + m00.y * a.x + m01.x * b.y + m01.y * b.x;
    nb.x = m10.x * a.x - m10.y * a.y + m11.x * b.x - m11.y * b.y;
    nb.y = m10.x * a.y + m10.y * a.x + m11.x * b.y + m11.y * b.x;
    a = na; b = nb;
}

// Apply one "block" (4 layers x 4 qubits) to a 16-amplitude state in registers.
// params p: 48 floats, layout [layer][qubit][3].
// Qubit q has linear-index stride (8 >> q) (tensor axis 0 = MSB).
__device__ __forceinline__ void apply_block(float2 s[16], const float p[48]) {
    // Layer 0: single-qubit Rot on each qubit.
    #pragma unroll
    for (int q = 0; q < 4; q++) {
        float2 m00, m01, m10, m11;
        rot_mat(p[q * 3 + 0], p[q * 3 + 1], p[q * 3 + 2], m00, m01, m10, m11);
        const int str = 8 >> q;
        #pragma unroll
        for (int i = 0; i < 16; i++) {
            if (i & str) continue;
            gate_pair(s[i], s[i + str], m00, m01, m10, m11);
        }
    }
    // Layers 1..3: CRot(control=q, target=(q+off)%4).
    #pragma unroll
    for (int off = 1; off <= 3; off++) {
        #pragma unroll
        for (int q = 0; q < 4; q++) {
            const int t = (q + off) & 3;
            const int base = (off * 4 + q) * 3;
            float2 m00, m01, m10, m11;
            rot_mat(p[base + 0], p[base + 1], p[base + 2], m00, m01, m10, m11);
            const int sc = 8 >> q;
            const int st = 8 >> t;
            #pragma unroll
            for (int i = 0; i < 16; i++) {
                if (!(i & sc) || (i & st)) continue;  // control must be 1, target bit 0
                gate_pair(s[i], s[i + st], m00, m01, m10, m11);
            }
        }
    }
}

__device__ __forceinline__ void load_params48(const float* __restrict__ g, float p[48]) {
    // 48 floats = 192 bytes, always 16B-aligned (entity index * 192).
    const float4* g4 = reinterpret_cast<const float4*>(g);
    #pragma unroll
    for (int i = 0; i < 12; i++) {
        float4 v = __ldg(g4 + i);
        p[i * 4 + 0] = v.x; p[i * 4 + 1] = v.y;
        p[i * 4 + 2] = v.z; p[i * 4 + 3] = v.w;
    }
}

// ---------------------------------------------------------------------------
// Kernel A: v_e = U(entity_params[e]) * s0  (s0 = uniform 0.25 after H^4)
// ---------------------------------------------------------------------------
__global__ void entity_kernel(const float* __restrict__ ep, int E) {
    int e = blockIdx.x * blockDim.x + threadIdx.x;
    if (e >= E) return;
    float p[48];
    load_params48(ep + (size_t)e * 48, p);
    float2 s[16];
    #pragma unroll
    for (int i = 0; i < 16; i++) s[i] = make_float2(0.25f, 0.0f);
    apply_block(s, p);
    float4* dst = reinterpret_cast<float4*>(g_ve + e * 16);
    #pragma unroll
    for (int i = 0; i < 8; i++)
        dst[i] = make_float4(s[2 * i].x, s[2 * i].y, s[2 * i + 1].x, s[2 * i + 1].y);
}

// ---------------------------------------------------------------------------
// Kernel B: M_r column j = U(relation_params[r]) * e_j.  One thread per (r, col).
// ---------------------------------------------------------------------------
__global__ void relation_kernel(const float* __restrict__ rp, int R) {
    int idx = blockIdx.x * blockDim.x + threadIdx.x;
    int r = idx >> 4;
    int col = idx & 15;
    if (r >= R) return;
    float p[48];
    load_params48(rp + (size_t)r * 48, p);
    float2 s[16];
    #pragma unroll
    for (int i = 0; i < 16; i++) s[i] = make_float2(0.0f, 0.0f);
    s[col] = make_float2(1.0f, 0.0f);
    apply_block(s, p);
    // Row-major M[r][i][j]; adjacent threads (same r) write consecutive j -> coalesced.
    #pragma unroll
    for (int i = 0; i < 16; i++)
        g_mr[r * 256 + i * 16 + col] = s[i];
}

// ---------------------------------------------------------------------------
// Kernel C: score_b = Re( v_t^dagger * M_r * v_h )
// ---------------------------------------------------------------------------
__global__ void score_kernel(const int* __restrict__ h, const int* __restrict__ r,
                             const int* __restrict__ t, float* __restrict__ out, int B) {
    int b = blockIdx.x * blockDim.x + threadIdx.x;
    if (b >= B) return;

    const float4* vh4 = reinterpret_cast<const float4*>(g_ve + (size_t)h[b] * 16);
    const float4* vt4 = reinterpret_cast<const float4*>(g_ve + (size_t)t[b] * 16);
    float2 vh[16], vt[16];
    #pragma unroll
    for (int i = 0; i < 8; i++) {
        float4 a = __ldg(vh4 + i);
        vh[2 * i]     = make_float2(a.x, a.y);
        vh[2 * i + 1] = make_float2(a.z, a.w);
        float4 c = __ldg(vt4 + i);
        vt[2 * i]     = make_float2(c.x, c.y);
        vt[2 * i + 1] = make_float2(c.z, c.w);
    }

    const float4* M4 = reinterpret_cast<const float4*>(g_mr + (size_t)r[b] * 256);
    float acc = 0.0f;
    #pragma unroll
    for (int i = 0; i < 16; i++) {
        float2 u = make_float2(0.0f, 0.0f);
        #pragma unroll
        for (int j4 = 0; j4 < 8; j4++) {  // 8 float4 per row = 16 complex
            float4 mm = __ldg(M4 + i * 8 + j4);
            float2 m0 = make_float2(mm.x, mm.y);
            float2 m1 = make_float2(mm.z, mm.w);
            float2 a0 = vh[2 * j4];
            float2 a1 = vh[2 * j4 + 1];
            u.x += m0.x * a0.x - m0.y * a0.y + m1.x * a1.x - m1.y * a1.y;
            u.y += m0.x * a0.y + m0.y * a0.x + m1.x * a1.y + m1.y * a1.x;
        }
        // Re( conj(vt[i]) * u )
        acc += vt[i].x * u.x + vt[i].y * u.y;
    }
    out[b] = acc;
}

// ---------------------------------------------------------------------------
// Launch
// ---------------------------------------------------------------------------
extern "C" void kernel_launch(void* const* d_in, const int* in_sizes, int n_in,
                              void* d_out, int out_size) {
    const float* ep = (const float*)d_in[0];  // entity_params   [E,4,4,3]
    const float* rp = (const float*)d_in[1];  // relation_params [R,4,4,3]
    const int* h = (const int*)d_in[2];
    const int* r = (const int*)d_in[3];
    const int* t = (const int*)d_in[4];
    float* out = (float*)d_out;

    int E = in_sizes[0] / 48;
    int R = in_sizes[1] / 48;
    int B = in_sizes[2];

    entity_kernel<<<(E + 255) / 256, 256>>>(ep, E);
    relation_kernel<<<(R * 16 + 255) / 256, 256>>>(rp, R);
    score_kernel<<<(B + 255) / 256, 256>>>(h, r, t, out, B);
}

// round 2
// speedup vs baseline: 1.6126x; 1.6126x over previous
#include <cuda_runtime.h>

// Problem constants (shapes fixed by the dataset).
#define NE_MAX 100000
#define NR_MAX 1000
#define NB_MAX 131072

// Scratch (allocation-free: __device__ globals).
__device__ float2 g_ve[NE_MAX * 16];   // 12.8 MB per-entity state vectors
__device__ float2 g_mr[NR_MAX * 256];  // 2.0 MB per-relation 16x16 matrices (row-major)
__device__ int g_hist[NR_MAX];         // relation counts
__device__ int g_cursor[NR_MAX];       // running offsets during scatter
__device__ int g_perm[NB_MAX];         // batch indices sorted by relation

// ---------------------------------------------------------------------------
// Gate math. All rotation-angle arguments lie in [-pi/10, pi/10] (dataset init
// range), so the fast __sincosf intrinsic (abs err ~2^-21) is safely within
// the 1e-3 rel-err budget and avoids libm range reduction entirely.
// ---------------------------------------------------------------------------
__device__ __forceinline__ void rot_mat(float phi, float th, float om,
                                        float2& m00, float2& m01,
                                        float2& m10, float2& m11) {
    float st, ct, sa, ca, sb, cb;
    __sincosf(0.5f * th, &st, &ct);
    __sincosf(0.5f * (phi + om), &sa, &ca);
    __sincosf(0.5f * (phi - om), &sb, &cb);
    m00 = make_float2(ca * ct, -sa * ct);
    m01 = make_float2(-cb * st, -sb * st);
    m10 = make_float2(cb * st, -sb * st);
    m11 = make_float2(ca * ct, sa * ct);
}

__device__ __forceinline__ void gate_pair(float2& a, float2& b,
                                          float2 m00, float2 m01,
                                          float2 m10, float2 m11) {
    float2 na, nb;
    na.x = m00.x * a.x - m00.y * a.y + m01.x * b.x - m01.y * b.y;
    na.y = m00.x * a.y + m00.y * a.x + m01.x * b.y + m01.y * b.x;
    nb.x = m10.x * a.x - m10.y * a.y + m11.x * b.x - m11.y * b.y;
    nb.y = m10.x * a.y + m10.y * a.x + m11.x * b.y + m11.y * b.x;
    a = na; b = nb;
}

// One "block" (4 layers x 4 qubits) on a 16-amplitude register state.
// Qubit q has linear-index stride (8 >> q) (tensor axis 0 = MSB).
__device__ __forceinline__ void apply_block(float2 s[16], const float p[48]) {
    #pragma unroll
    for (int q = 0; q < 4; q++) {
        float2 m00, m01, m10, m11;
        rot_mat(p[q * 3 + 0], p[q * 3 + 1], p[q * 3 + 2], m00, m01, m10, m11);
        const int str = 8 >> q;
        #pragma unroll
        for (int i = 0; i < 16; i++) {
            if (i & str) continue;
            gate_pair(s[i], s[i + str], m00, m01, m10, m11);
        }
    }
    #pragma unroll
    for (int off = 1; off <= 3; off++) {
        #pragma unroll
        for (int q = 0; q < 4; q++) {
            const int t = (q + off) & 3;
            const int base = (off * 4 + q) * 3;
            float2 m00, m01, m10, m11;
            rot_mat(p[base + 0], p[base + 1], p[base + 2], m00, m01, m10, m11);
            const int sc = 8 >> q;
            const int st = 8 >> t;
            #pragma unroll
            for (int i = 0; i < 16; i++) {
                if (!(i & sc) || (i & st)) continue;  // control=1, target bit=0
                gate_pair(s[i], s[i + st], m00, m01, m10, m11);
            }
        }
    }
}

__device__ __forceinline__ void load_params48(const float* __restrict__ g, float p[48]) {
    const float4* g4 = reinterpret_cast<const float4*>(g);
    #pragma unroll
    for (int i = 0; i < 12; i++) {
        float4 v = __ldg(g4 + i);
        p[i * 4 + 0] = v.x; p[i * 4 + 1] = v.y;
        p[i * 4 + 2] = v.z; p[i * 4 + 3] = v.w;
    }
}

// ---------------------------------------------------------------------------
// Kernel A: v_e = U(entity_params[e]) * s0   (s0 uniform 0.25 after H^4)
// ---------------------------------------------------------------------------
__global__ void entity_kernel(const float* __restrict__ ep, int E) {
    int e = blockIdx.x * blockDim.x + threadIdx.x;
    if (e >= E) return;
    float p[48];
    load_params48(ep + (size_t)e * 48, p);
    float2 s[16];
    #pragma unroll
    for (int i = 0; i < 16; i++) s[i] = make_float2(0.25f, 0.0f);
    apply_block(s, p);
    float4* dst = reinterpret_cast<float4*>(g_ve + e * 16);
    #pragma unroll
    for (int i = 0; i < 8; i++)
        dst[i] = make_float4(s[2 * i].x, s[2 * i].y, s[2 * i + 1].x, s[2 * i + 1].y);
}

// ---------------------------------------------------------------------------
// Kernel B: M_r column j = U(relation_params[r]) * e_j.  One thread per (r,col).
// ---------------------------------------------------------------------------
__global__ void relation_kernel(const float* __restrict__ rp, int R) {
    int idx = blockIdx.x * blockDim.x + threadIdx.x;
    int r = idx >> 4;
    int col = idx & 15;
    if (r >= R) return;
    float p[48];
    load_params48(rp + (size_t)r * 48, p);
    float2 s[16];
    #pragma unroll
    for (int i = 0; i < 16; i++) s[i] = make_float2(0.0f, 0.0f);
    s[col] = make_float2(1.0f, 0.0f);
    apply_block(s, p);
    #pragma unroll
    for (int i = 0; i < 16; i++)
        g_mr[r * 256 + i * 16 + col] = s[i];
}

// ---------------------------------------------------------------------------
// Sort-by-relation pipeline (so score-kernel warps see warp-uniform r, making
// all M loads broadcast: 1 wavefront per load instead of ~32).
// ---------------------------------------------------------------------------
__global__ void zero_kernel(int R) {
    int i = blockIdx.x * blockDim.x + threadIdx.x;
    if (i < R) g_hist[i] = 0;
}

__global__ void hist_kernel(const int* __restrict__ r, int B) {
    int b = blockIdx.x * blockDim.x + threadIdx.x;
    if (b < B) atomicAdd(&g_hist[r[b]], 1);
}

// Single-block exclusive prefix sum over R<=1024 bins -> g_cursor.
__global__ void scan_kernel(int R) {
    __shared__ int buf[1024];
    int t = threadIdx.x;
    int v = (t < R) ? g_hist[t] : 0;
    buf[t] = v;
    __syncthreads();
    #pragma unroll
    for (int d = 1; d < 1024; d <<= 1) {
        int x = (t >= d) ? buf[t - d] : 0;
        __syncthreads();
        buf[t] += x;
        __syncthreads();
    }
    if (t < R) g_cursor[t] = buf[t] - v;  // exclusive
}

__global__ void scatter_kernel(const int* __restrict__ r, int B) {
    int b = blockIdx.x * blockDim.x + threadIdx.x;
    if (b < B) {
        int pos = atomicAdd(&g_cursor[r[b]], 1);
        g_perm[pos] = b;
    }
}

// ---------------------------------------------------------------------------
// Kernel C: score_b = Re( v_t^dagger * M_r * v_h ), processed in sorted order.
// ---------------------------------------------------------------------------
__global__ void score_kernel(const int* __restrict__ h, const int* __restrict__ r,
                             const int* __restrict__ t, float* __restrict__ out, int B) {
    int idx = blockIdx.x * blockDim.x + threadIdx.x;
    if (idx >= B) return;
    int b = g_perm[idx];

    const float4* vh4 = reinterpret_cast<const float4*>(g_ve + (size_t)h[b] * 16);
    const float4* vt4 = reinterpret_cast<const float4*>(g_ve + (size_t)t[b] * 16);
    float2 vh[16], vt[16];
    #pragma unroll
    for (int i = 0; i < 8; i++) {
        float4 a = __ldg(vh4 + i);
        vh[2 * i]     = make_float2(a.x, a.y);
        vh[2 * i + 1] = make_float2(a.z, a.w);
        float4 c = __ldg(vt4 + i);
        vt[2 * i]     = make_float2(c.x, c.y);
        vt[2 * i + 1] = make_float2(c.z, c.w);
    }

    // Warp-uniform M pointer (lanes share r after sorting) -> broadcast loads.
    const float4* M4 = reinterpret_cast<const float4*>(g_mr + (size_t)r[b] * 256);
    float acc = 0.0f;
    #pragma unroll
    for (int i = 0; i < 16; i++) {
        float2 u = make_float2(0.0f, 0.0f);
        #pragma unroll
        for (int j4 = 0; j4 < 8; j4++) {
            float4 mm = __ldg(M4 + i * 8 + j4);
            float2 m0 = make_float2(mm.x, mm.y);
            float2 m1 = make_float2(mm.z, mm.w);
            float2 a0 = vh[2 * j4];
            float2 a1 = vh[2 * j4 + 1];
            u.x += m0.x * a0.x - m0.y * a0.y + m1.x * a1.x - m1.y * a1.y;
            u.y += m0.x * a0.y + m0.y * a0.x + m1.x * a1.y + m1.y * a1.x;
        }
        acc += vt[i].x * u.x + vt[i].y * u.y;  // Re(conj(vt_i) * u_i)
    }
    out[b] = acc;
}

// ---------------------------------------------------------------------------
// Launch
// ---------------------------------------------------------------------------
extern "C" void kernel_launch(void* const* d_in, const int* in_sizes, int n_in,
                              void* d_out, int out_size) {
    const float* ep = (const float*)d_in[0];  // entity_params   [E,4,4,3]
    const float* rp = (const float*)d_in[1];  // relation_params [R,4,4,3]
    const int* h = (const int*)d_in[2];
    const int* r = (const int*)d_in[3];
    const int* t = (const int*)d_in[4];
    float* out = (float*)d_out;

    int E = in_sizes[0] / 48;
    int R = in_sizes[1] / 48;
    int B = in_sizes[2];

    entity_kernel<<<(E + 255) / 256, 256>>>(ep, E);
    relation_kernel<<<(R * 16 + 255) / 256, 256>>>(rp, R);

    zero_kernel<<<(R + 255) / 256, 256>>>(R);
    hist_kernel<<<(B + 255) / 256, 256>>>(r, B);
    scan_kernel<<<1, 1024>>>(R);
    scatter_kernel<<<(B + 255) / 256, 256>>>(r, B);

    score_kernel<<<(B + 255) / 256, 256>>>(h, r, t, out, B);
}

// round 5
// speedup vs baseline: 2.1629x; 1.3412x over previous
#include <cuda_runtime.h>

// Problem constants (shapes fixed by the dataset).
#define NE_MAX 100000
#define NR_MAX 1000
#define NB_MAX 131072

// Scratch (allocation-free: __device__ globals, zero-initialized at load).
__device__ float2 g_ve[NE_MAX * 16];   // 12.8 MB per-entity state vectors
__device__ float2 g_mr[NR_MAX * 256];  // 2.0 MB per-relation 16x16 matrices
__device__ int g_hist[NR_MAX];         // relation counts (INVARIANT: zero at kernel_launch entry)
__device__ int g_cursor[NR_MAX];       // running offsets during scatter
__device__ int g_perm[NB_MAX];         // batch indices grouped by relation

// ---------------------------------------------------------------------------
// Gate math. Angles are in [-pi/10, pi/10] -> __sincosf (abs err ~2^-21) is
// well inside the 1e-3 budget and skips libm range reduction.
// ---------------------------------------------------------------------------
__device__ __forceinline__ void rot_mat(float phi, float th, float om,
                                        float2& m00, float2& m01,
                                        float2& m10, float2& m11) {
    float st, ct, sa, ca, sb, cb;
    __sincosf(0.5f * th, &st, &ct);
    __sincosf(0.5f * (phi + om), &sa, &ca);
    __sincosf(0.5f * (phi - om), &sb, &cb);
    m00 = make_float2(ca * ct, -sa * ct);
    m01 = make_float2(-cb * st, -sb * st);
    m10 = make_float2(cb * st, -sb * st);
    m11 = make_float2(ca * ct, sa * ct);
}

__device__ __forceinline__ void gate_pair(float2& a, float2& b,
                                          float2 m00, float2 m01,
                                          float2 m10, float2 m11) {
    float2 na, nb;
    na.x = m00.x * a.x - m00.y * a.y + m01.x * b.x - m01.y * b.y;
    na.y = m00.x * a.y + m00.y * a.x + m01.x * b.y + m01.y * b.x;
    nb.x = m10.x * a.x - m10.y * a.y + m11.x * b.x - m11.y * b.y;
    nb.y = m10.x * a.y + m10.y * a.x + m11.x * b.y + m11.y * b.x;
    a = na; b = nb;
}

// One "block" (4 layers x 4 qubits) on a 16-amplitude register state.
// Qubit q has linear-index stride (8 >> q) (tensor axis 0 = MSB).
__device__ __forceinline__ void apply_block(float2 s[16], const float p[48]) {
    #pragma unroll
    for (int q = 0; q < 4; q++) {
        float2 m00, m01, m10, m11;
        rot_mat(p[q * 3 + 0], p[q * 3 + 1], p[q * 3 + 2], m00, m01, m10, m11);
        const int str = 8 >> q;
        #pragma unroll
        for (int i = 0; i < 16; i++) {
            if (i & str) continue;
            gate_pair(s[i], s[i + str], m00, m01, m10, m11);
        }
    }
    #pragma unroll
    for (int off = 1; off <= 3; off++) {
        #pragma unroll
        for (int q = 0; q < 4; q++) {
            const int t = (q + off) & 3;
            const int base = (off * 4 + q) * 3;
            float2 m00, m01, m10, m11;
            rot_mat(p[base + 0], p[base + 1], p[base + 2], m00, m01, m10, m11);
            const int sc = 8 >> q;
            const int st = 8 >> t;
            #pragma unroll
            for (int i = 0; i < 16; i++) {
                if (!(i & sc) || (i & st)) continue;  // control=1, target bit=0
                gate_pair(s[i], s[i + st], m00, m01, m10, m11);
            }
        }
    }
}

__device__ __forceinline__ void load_params48(const float* __restrict__ g, float p[48]) {
    const float4* g4 = reinterpret_cast<const float4*>(g);
    #pragma unroll
    for (int i = 0; i < 12; i++) {
        float4 v = __ldg(g4 + i);
        p[i * 4 + 0] = v.x; p[i * 4 + 1] = v.y;
        p[i * 4 + 2] = v.z; p[i * 4 + 3] = v.w;
    }
}

// ---------------------------------------------------------------------------
// Fused prep kernel: three independent jobs split by blockIdx range.
//   [0, EB)          : entity state vectors  v_e = U(ep[e]) * s0
//   [EB, EB+RB)      : relation matrices     M_r (one thread per (r, col))
//   [EB+RB, +HB)     : relation histogram (smem-privatized)
// ---------------------------------------------------------------------------
#define HIST_BLOCKS 64

__global__ void prep_kernel(const float* __restrict__ ep, int E, int EB,
                            const float* __restrict__ rp, int R, int RB,
                            const int* __restrict__ r, int B) {
    __shared__ int sh[NR_MAX];

    if (blockIdx.x < EB) {
        // ---- entity job ----
        int e = blockIdx.x * blockDim.x + threadIdx.x;
        if (e >= E) return;
        float p[48];
        load_params48(ep + (size_t)e * 48, p);
        float2 s[16];
        #pragma unroll
        for (int i = 0; i < 16; i++) s[i] = make_float2(0.25f, 0.0f);
        apply_block(s, p);
        float4* dst = reinterpret_cast<float4*>(g_ve + e * 16);
        #pragma unroll
        for (int i = 0; i < 8; i++)
            dst[i] = make_float4(s[2 * i].x, s[2 * i].y, s[2 * i + 1].x, s[2 * i + 1].y);
    } else if (blockIdx.x < EB + RB) {
        // ---- relation job ----
        int idx = (blockIdx.x - EB) * blockDim.x + threadIdx.x;
        int rr = idx >> 4;
        int col = idx & 15;
        if (rr >= R) return;
        float p[48];
        load_params48(rp + (size_t)rr * 48, p);
        float2 s[16];
        #pragma unroll
        for (int i = 0; i < 16; i++) s[i] = make_float2(0.0f, 0.0f);
        s[col] = make_float2(1.0f, 0.0f);
        apply_block(s, p);
        #pragma unroll
        for (int i = 0; i < 16; i++)
            g_mr[rr * 256 + i * 16 + col] = s[i];
    } else {
        // ---- histogram job (smem-privatized; g_hist is zero at entry) ----
        int hb = blockIdx.x - EB - RB;                    // 0..HIST_BLOCKS-1
        for (int i = threadIdx.x; i < NR_MAX; i += blockDim.x) sh[i] = 0;
        __syncthreads();
        int chunk = (B + HIST_BLOCKS - 1) / HIST_BLOCKS;
        int start = hb * chunk;
        int end = min(start + chunk, B);
        for (int b = start + threadIdx.x; b < end; b += blockDim.x)
            atomicAdd(&sh[r[b]], 1);
        __syncthreads();
        for (int i = threadIdx.x; i < NR_MAX; i += blockDim.x) {
            int c = sh[i];
            if (c) atomicAdd(&g_hist[i], c);
        }
    }
}

// ---------------------------------------------------------------------------
// Exclusive scan of g_hist -> g_cursor; re-zeroes g_hist (replay invariant).
// Single block, 1024 threads, R <= 1024.
// ---------------------------------------------------------------------------
__global__ void scan_kernel(int R) {
    __shared__ int warp_sums[32];
    int t = threadIdx.x;
    int v = (t < R) ? g_hist[t] : 0;
    int x = v;
    #pragma unroll
    for (int d = 1; d < 32; d <<= 1) {
        int y = __shfl_up_sync(0xffffffffu, x, d);
        if ((t & 31) >= d) x += y;
    }
    if ((t & 31) == 31) warp_sums[t >> 5] = x;
    __syncthreads();
    if (t < 32) {
        int s = warp_sums[t];
        #pragma unroll
        for (int d = 1; d < 32; d <<= 1) {
            int y = __shfl_up_sync(0xffffffffu, s, d);
            if (t >= d) s += y;
        }
        warp_sums[t] = s;
    }
    __syncthreads();
    int base = (t >= 32) ? warp_sums[(t >> 5) - 1] : 0;
    if (t < R) {
        g_cursor[t] = base + x - v;  // exclusive prefix
        g_hist[t] = 0;               // restore invariant for next replay
    }
}

// ---------------------------------------------------------------------------
// Block-aggregated scatter: per-block smem counts, one range-reservation
// atomic per nonzero bin, then local-offset placement.
// ---------------------------------------------------------------------------
#define SCAT_BLOCKS 64

__global__ void scatter_kernel(const int* __restrict__ r, int B) {
    __shared__ int cnt[NR_MAX];
    __shared__ int base[NR_MAX];
    for (int i = threadIdx.x; i < NR_MAX; i += blockDim.x) cnt[i] = 0;
    __syncthreads();

    int chunk = (B + SCAT_BLOCKS - 1) / SCAT_BLOCKS;
    int start = blockIdx.x * chunk;
    int end = min(start + chunk, B);

    for (int b = start + threadIdx.x; b < end; b += blockDim.x)
        atomicAdd(&cnt[r[b]], 1);
    __syncthreads();

    for (int i = threadIdx.x; i < NR_MAX; i += blockDim.x) {
        int c = cnt[i];
        base[i] = c ? atomicAdd(&g_cursor[i], c) : 0;
        cnt[i] = 0;
    }
    __syncthreads();

    for (int b = start + threadIdx.x; b < end; b += blockDim.x) {
        int rr = r[b];
        int pos = base[rr] + atomicAdd(&cnt[rr], 1);
        g_perm[pos] = b;
    }
}

// ---------------------------------------------------------------------------
// Score: score_b = Re( v_t^dagger * M_r * v_h ), in relation-grouped order so
// M loads are warp-uniform broadcasts.
// ---------------------------------------------------------------------------
__global__ void score_kernel(const int* __restrict__ h, const int* __restrict__ r,
                             const int* __restrict__ t, float* __restrict__ out, int B) {
    int idx = blockIdx.x * blockDim.x + threadIdx.x;
    if (idx >= B) return;
    int b = g_perm[idx];

    const float4* vh4 = reinterpret_cast<const float4*>(g_ve + (size_t)h[b] * 16);
    const float4* vt4 = reinterpret_cast<const float4*>(g_ve + (size_t)t[b] * 16);
    float2 vh[16], vt[16];
    #pragma unroll
    for (int i = 0; i < 8; i++) {
        float4 a = __ldg(vh4 + i);
        vh[2 * i]     = make_float2(a.x, a.y);
        vh[2 * i + 1] = make_float2(a.z, a.w);
        float4 c = __ldg(vt4 + i);
        vt[2 * i]     = make_float2(c.x, c.y);
        vt[2 * i + 1] = make_float2(c.z, c.w);
    }

    const float4* M4 = reinterpret_cast<const float4*>(g_mr + (size_t)r[b] * 256);
    float acc = 0.0f;
    #pragma unroll
    for (int i = 0; i < 16; i++) {
        float2 u = make_float2(0.0f, 0.0f);
        #pragma unroll
        for (int j4 = 0; j4 < 8; j4++) {
            float4 mm = __ldg(M4 + i * 8 + j4);
            float2 m0 = make_float2(mm.x, mm.y);
            float2 m1 = make_float2(mm.z, mm.w);
            float2 a0 = vh[2 * j4];
            float2 a1 = vh[2 * j4 + 1];
            u.x += m0.x * a0.x - m0.y * a0.y + m1.x * a1.x - m1.y * a1.y;
            u.y += m0.x * a0.y + m0.y * a0.x + m1.x * a1.y + m1.y * a1.x;
        }
        acc += vt[i].x * u.x + vt[i].y * u.y;  // Re(conj(vt_i) * u_i)
    }
    out[b] = acc;
}

// ---------------------------------------------------------------------------
// Launch: 4 kernels total (prep -> scan -> scatter -> score).
// ---------------------------------------------------------------------------
extern "C" void kernel_launch(void* const* d_in, const int* in_sizes, int n_in,
                              void* d_out, int out_size) {
    const float* ep = (const float*)d_in[0];  // entity_params   [E,4,4,3]
    const float* rp = (const float*)d_in[1];  // relation_params [R,4,4,3]
    const int* h = (const int*)d_in[2];
    const int* r = (const int*)d_in[3];
    const int* t = (const int*)d_in[4];
    float* out = (float*)d_out;

    int E = in_sizes[0] / 48;
    int R = in_sizes[1] / 48;
    int B = in_sizes[2];

    int EB = (E + 255) / 256;
    int RB = (R * 16 + 255) / 256;

    prep_kernel<<<EB + RB + HIST_BLOCKS, 256>>>(ep, E, EB, rp, R, RB, r, B);
    scan_kernel<<<1, 1024>>>(R);
    scatter_kernel<<<SCAT_BLOCKS, 256>>>(r, B);
    score_kernel<<<(B + 255) / 256, 256>>>(h, r, t, out, B);
}

// round 6
// speedup vs baseline: 2.3494x; 1.0862x over previous
#include <cuda_runtime.h>

// Problem constants (shapes fixed by the dataset).
#define NE_MAX 100000
#define NR_MAX 1000
#define NB_MAX 131072

// Scratch (allocation-free: __device__ globals, zero-initialized at load).
__device__ float2 g_ve[NE_MAX * 16];   // 12.8 MB per-entity state vectors
__device__ float2 g_mr[NR_MAX * 256];  // 2.0 MB per-relation 16x16 matrices
__device__ int g_hist[NR_MAX];         // relation counts (INVARIANT: zero at entry)
__device__ int g_cursor[NR_MAX];       // running offsets during scatter
__device__ int4 g_pack[NB_MAX];        // relation-grouped {b, h[b], r[b], t[b]}

// ---------------------------------------------------------------------------
// Gate math. Angles in [-pi/10, pi/10] -> __sincosf is inside the 1e-3 budget.
// ---------------------------------------------------------------------------
__device__ __forceinline__ void rot_mat(float phi, float th, float om,
                                        float2& m00, float2& m01,
                                        float2& m10, float2& m11) {
    float st, ct, sa, ca, sb, cb;
    __sincosf(0.5f * th, &st, &ct);
    __sincosf(0.5f * (phi + om), &sa, &ca);
    __sincosf(0.5f * (phi - om), &sb, &cb);
    m00 = make_float2(ca * ct, -sa * ct);
    m01 = make_float2(-cb * st, -sb * st);
    m10 = make_float2(cb * st, -sb * st);
    m11 = make_float2(ca * ct, sa * ct);
}

__device__ __forceinline__ void gate_pair(float2& a, float2& b,
                                          float2 m00, float2 m01,
                                          float2 m10, float2 m11) {
    float2 na, nb;
    na.x = m00.x * a.x - m00.y * a.y + m01.x * b.x - m01.y * b.y;
    na.y = m00.x * a.y + m00.y * a.x + m01.x * b.y + m01.y * b.x;
    nb.x = m10.x * a.x - m10.y * a.y + m11.x * b.x - m11.y * b.y;
    nb.y = m10.x * a.y + m10.y * a.x + m11.x * b.y + m11.y * b.x;
    a = na; b = nb;
}

// One "block" (4 layers x 4 qubits) on a 16-amplitude register state.
__device__ __forceinline__ void apply_block(float2 s[16], const float p[48]) {
    #pragma unroll
    for (int q = 0; q < 4; q++) {
        float2 m00, m01, m10, m11;
        rot_mat(p[q * 3 + 0], p[q * 3 + 1], p[q * 3 + 2], m00, m01, m10, m11);
        const int str = 8 >> q;
        #pragma unroll
        for (int i = 0; i < 16; i++) {
            if (i & str) continue;
            gate_pair(s[i], s[i + str], m00, m01, m10, m11);
        }
    }
    #pragma unroll
    for (int off = 1; off <= 3; off++) {
        #pragma unroll
        for (int q = 0; q < 4; q++) {
            const int t = (q + off) & 3;
            const int base = (off * 4 + q) * 3;
            float2 m00, m01, m10, m11;
            rot_mat(p[base + 0], p[base + 1], p[base + 2], m00, m01, m10, m11);
            const int sc = 8 >> q;
            const int st = 8 >> t;
            #pragma unroll
            for (int i = 0; i < 16; i++) {
                if (!(i & sc) || (i & st)) continue;  // control=1, target bit=0
                gate_pair(s[i], s[i + st], m00, m01, m10, m11);
            }
        }
    }
}

__device__ __forceinline__ void load_params48(const float* __restrict__ g, float p[48]) {
    const float4* g4 = reinterpret_cast<const float4*>(g);
    #pragma unroll
    for (int i = 0; i < 12; i++) {
        float4 v = __ldg(g4 + i);
        p[i * 4 + 0] = v.x; p[i * 4 + 1] = v.y;
        p[i * 4 + 2] = v.z; p[i * 4 + 3] = v.w;
    }
}

// ---------------------------------------------------------------------------
// Fused prep kernel: entities | relations | histogram, split by blockIdx.
// ---------------------------------------------------------------------------
#define HIST_BLOCKS 64

__global__ void prep_kernel(const float* __restrict__ ep, int E, int EB,
                            const float* __restrict__ rp, int R, int RB,
                            const int* __restrict__ r, int B) {
    __shared__ int sh[NR_MAX];

    if (blockIdx.x < EB) {
        int e = blockIdx.x * blockDim.x + threadIdx.x;
        if (e >= E) return;
        float p[48];
        load_params48(ep + (size_t)e * 48, p);
        float2 s[16];
        #pragma unroll
        for (int i = 0; i < 16; i++) s[i] = make_float2(0.25f, 0.0f);
        apply_block(s, p);
        float4* dst = reinterpret_cast<float4*>(g_ve + e * 16);
        #pragma unroll
        for (int i = 0; i < 8; i++)
            dst[i] = make_float4(s[2 * i].x, s[2 * i].y, s[2 * i + 1].x, s[2 * i + 1].y);
    } else if (blockIdx.x < EB + RB) {
        int idx = (blockIdx.x - EB) * blockDim.x + threadIdx.x;
        int rr = idx >> 4;
        int col = idx & 15;
        if (rr >= R) return;
        float p[48];
        load_params48(rp + (size_t)rr * 48, p);
        float2 s[16];
        #pragma unroll
        for (int i = 0; i < 16; i++) s[i] = make_float2(0.0f, 0.0f);
        s[col] = make_float2(1.0f, 0.0f);
        apply_block(s, p);
        #pragma unroll
        for (int i = 0; i < 16; i++)
            g_mr[rr * 256 + i * 16 + col] = s[i];
    } else {
        int hb = blockIdx.x - EB - RB;
        for (int i = threadIdx.x; i < NR_MAX; i += blockDim.x) sh[i] = 0;
        __syncthreads();
        int chunk = (B + HIST_BLOCKS - 1) / HIST_BLOCKS;
        int start = hb * chunk;
        int end = min(start + chunk, B);
        for (int b = start + threadIdx.x; b < end; b += blockDim.x)
            atomicAdd(&sh[r[b]], 1);
        __syncthreads();
        for (int i = threadIdx.x; i < NR_MAX; i += blockDim.x) {
            int c = sh[i];
            if (c) atomicAdd(&g_hist[i], c);
        }
    }
}

// ---------------------------------------------------------------------------
// Exclusive scan g_hist -> g_cursor; re-zero g_hist (graph-replay invariant).
// ---------------------------------------------------------------------------
__global__ void scan_kernel(int R) {
    __shared__ int warp_sums[32];
    int t = threadIdx.x;
    int v = (t < R) ? g_hist[t] : 0;
    int x = v;
    #pragma unroll
    for (int d = 1; d < 32; d <<= 1) {
        int y = __shfl_up_sync(0xffffffffu, x, d);
        if ((t & 31) >= d) x += y;
    }
    if ((t & 31) == 31) warp_sums[t >> 5] = x;
    __syncthreads();
    if (t < 32) {
        int s = warp_sums[t];
        #pragma unroll
        for (int d = 1; d < 32; d <<= 1) {
            int y = __shfl_up_sync(0xffffffffu, s, d);
            if (t >= d) s += y;
        }
        warp_sums[t] = s;
    }
    __syncthreads();
    int base = (t >= 32) ? warp_sums[(t >> 5) - 1] : 0;
    if (t < R) {
        g_cursor[t] = base + x - v;
        g_hist[t] = 0;
    }
}

// ---------------------------------------------------------------------------
// Block-aggregated scatter. Writes the packed record {b, h[b], r[b], t[b]} so
// score has zero scattered reads (one scattered STG.128 here instead).
// ---------------------------------------------------------------------------
#define SCAT_BLOCKS 64

__global__ void scatter_kernel(const int* __restrict__ h, const int* __restrict__ r,
                               const int* __restrict__ t, int B) {
    __shared__ int cnt[NR_MAX];
    __shared__ int base[NR_MAX];
    for (int i = threadIdx.x; i < NR_MAX; i += blockDim.x) cnt[i] = 0;
    __syncthreads();

    int chunk = (B + SCAT_BLOCKS - 1) / SCAT_BLOCKS;
    int start = blockIdx.x * chunk;
    int end = min(start + chunk, B);

    for (int b = start + threadIdx.x; b < end; b += blockDim.x)
        atomicAdd(&cnt[r[b]], 1);
    __syncthreads();

    for (int i = threadIdx.x; i < NR_MAX; i += blockDim.x) {
        int c = cnt[i];
        base[i] = c ? atomicAdd(&g_cursor[i], c) : 0;
        cnt[i] = 0;
    }
    __syncthreads();

    for (int b = start + threadIdx.x; b < end; b += blockDim.x) {
        int rr = r[b];
        int pos = base[rr] + atomicAdd(&cnt[rr], 1);
        g_pack[pos] = make_int4(b, h[b], rr, t[b]);
    }
}

// ---------------------------------------------------------------------------
// Score: score_b = Re( v_t^dagger * M_r * v_h ), relation-grouped order.
// v-vectors (one 128B line each) are staged into smem with warp-cooperative
// coalesced loads: 1 L1 wavefront per line instead of 8.
// ---------------------------------------------------------------------------
#define SCORE_ITEMS 128   // items per block == threads per block

__global__ void __launch_bounds__(SCORE_ITEMS) score_kernel(float* __restrict__ out, int B) {
    __shared__ float4 sv_h[SCORE_ITEMS * 8];  // 16 KB, swizzled chunks
    __shared__ float4 sv_t[SCORE_ITEMS * 8];  // 16 KB
    __shared__ int sh_h[SCORE_ITEMS];
    __shared__ int sh_t[SCORE_ITEMS];

    const int tid = threadIdx.x;
    const int start = blockIdx.x * SCORE_ITEMS;
    const int idx = start + tid;

    int b = -1, rr = 0;
    if (idx < B) {
        int4 pk = __ldg(&g_pack[idx]);   // coalesced: {b, h, r, t}
        b = pk.x; rr = pk.z;
        sh_h[tid] = pk.y;
        sh_t[tid] = pk.w;
    } else {
        sh_h[tid] = 0;
        sh_t[tid] = 0;
    }
    __syncthreads();

    // Cooperative staging: lane group of 8 loads one item's 128B line.
    // Swizzle chunk index by item so readback is conflict-free per warp quarter.
    const float4* ve4 = reinterpret_cast<const float4*>(g_ve);
    #pragma unroll
    for (int p = 0; p < 8; p++) {
        int i = p * SCORE_ITEMS + tid;
        int item = i >> 3;
        int chunk = i & 7;
        int sw = item * 8 + ((chunk + item) & 7);
        sv_h[sw] = __ldg(ve4 + (size_t)sh_h[item] * 8 + chunk);
        sv_t[sw] = __ldg(ve4 + (size_t)sh_t[item] * 8 + chunk);
    }
    __syncthreads();

    if (b < 0) return;

    // Pull this item's vectors into registers (conflict-free swizzled LDS.128).
    float2 vh[16], vt[16];
    #pragma unroll
    for (int j = 0; j < 8; j++) {
        float4 a = sv_h[tid * 8 + ((j + tid) & 7)];
        vh[2 * j]     = make_float2(a.x, a.y);
        vh[2 * j + 1] = make_float2(a.z, a.w);
        float4 c = sv_t[tid * 8 + ((j + tid) & 7)];
        vt[2 * j]     = make_float2(c.x, c.y);
        vt[2 * j + 1] = make_float2(c.z, c.w);
    }

    // M loads are warp-uniform (items grouped by relation) -> broadcast.
    const float4* M4 = reinterpret_cast<const float4*>(g_mr + (size_t)rr * 256);
    float acc = 0.0f;
    #pragma unroll
    for (int i = 0; i < 16; i++) {
        float2 u = make_float2(0.0f, 0.0f);
        #pragma unroll
        for (int j4 = 0; j4 < 8; j4++) {
            float4 mm = __ldg(M4 + i * 8 + j4);
            float2 a0 = vh[2 * j4];
            float2 a1 = vh[2 * j4 + 1];
            u.x += mm.x * a0.x - mm.y * a0.y + mm.z * a1.x - mm.w * a1.y;
            u.y += mm.x * a0.y + mm.y * a0.x + mm.z * a1.y + mm.w * a1.x;
        }
        acc += vt[i].x * u.x + vt[i].y * u.y;  // Re(conj(vt_i) * u_i)
    }
    out[b] = acc;
}

// ---------------------------------------------------------------------------
// Launch: prep -> scan -> scatter -> score.
// ---------------------------------------------------------------------------
extern "C" void kernel_launch(void* const* d_in, const int* in_sizes, int n_in,
                              void* d_out, int out_size) {
    const float* ep = (const float*)d_in[0];  // entity_params   [E,4,4,3]
    const float* rp = (const float*)d_in[1];  // relation_params [R,4,4,3]
    const int* h = (const int*)d_in[2];
    const int* r = (const int*)d_in[3];
    const int* t = (const int*)d_in[4];
    float* out = (float*)d_out;

    int E = in_sizes[0] / 48;
    int R = in_sizes[1] / 48;
    int B = in_sizes[2];

    int EB = (E + 255) / 256;
    int RB = (R * 16 + 255) / 256;

    prep_kernel<<<EB + RB + HIST_BLOCKS, 256>>>(ep, E, EB, rp, R, RB, r, B);
    scan_kernel<<<1, 1024>>>(R);
    scatter_kernel<<<SCAT_BLOCKS, 256>>>(h, r, t, B);
    score_kernel<<<(B + SCORE_ITEMS - 1) / SCORE_ITEMS, SCORE_ITEMS>>>(out, B);
}

// round 7
// speedup vs baseline: 2.6846x; 1.1426x over previous
#include <cuda_runtime.h>

// Problem constants (shapes fixed by the dataset).
#define NE_MAX 100000
#define NR_MAX 1000
#define NB_MAX 131072

// Scratch (allocation-free: __device__ globals, zero-initialized at load).
__device__ float2 g_ve[NE_MAX * 16];   // 12.8 MB per-entity state vectors
__device__ float2 g_mr[NR_MAX * 256];  // 2.0 MB per-relation 16x16 matrices
__device__ int g_hist[NR_MAX];         // relation counts (INVARIANT: zero at entry)
__device__ int g_cursor[NR_MAX];       // running offsets during scatter
__device__ int4 g_pack[NB_MAX];        // relation-grouped {b, h[b], r[b], t[b]}

// ---------------------------------------------------------------------------
// Gate math. Angles in [-pi/10, pi/10] -> __sincosf is inside the 1e-3 budget.
// ---------------------------------------------------------------------------
__device__ __forceinline__ void rot_mat(float phi, float th, float om,
                                        float2& m00, float2& m01,
                                        float2& m10, float2& m11) {
    float st, ct, sa, ca, sb, cb;
    __sincosf(0.5f * th, &st, &ct);
    __sincosf(0.5f * (phi + om), &sa, &ca);
    __sincosf(0.5f * (phi - om), &sb, &cb);
    m00 = make_float2(ca * ct, -sa * ct);
    m01 = make_float2(-cb * st, -sb * st);
    m10 = make_float2(cb * st, -sb * st);
    m11 = make_float2(ca * ct, sa * ct);
}

__device__ __forceinline__ void gate_pair(float2& a, float2& b,
                                          float2 m00, float2 m01,
                                          float2 m10, float2 m11) {
    float2 na, nb;
    na.x = m00.x * a.x - m00.y * a.y + m01.x * b.x - m01.y * b.y;
    na.y = m00.x * a.y + m00.y * a.x + m01.x * b.y + m01.y * b.x;
    nb.x = m10.x * a.x - m10.y * a.y + m11.x * b.x - m11.y * b.y;
    nb.y = m10.x * a.y + m10.y * a.x + m11.x * b.y + m11.y * b.x;
    a = na; b = nb;
}

// One "block" (4 layers x 4 qubits) on a 16-amplitude register state.
__device__ __forceinline__ void apply_block(float2 s[16], const float p[48]) {
    #pragma unroll
    for (int q = 0; q < 4; q++) {
        float2 m00, m01, m10, m11;
        rot_mat(p[q * 3 + 0], p[q * 3 + 1], p[q * 3 + 2], m00, m01, m10, m11);
        const int str = 8 >> q;
        #pragma unroll
        for (int i = 0; i < 16; i++) {
            if (i & str) continue;
            gate_pair(s[i], s[i + str], m00, m01, m10, m11);
        }
    }
    #pragma unroll
    for (int off = 1; off <= 3; off++) {
        #pragma unroll
        for (int q = 0; q < 4; q++) {
            const int t = (q + off) & 3;
            const int base = (off * 4 + q) * 3;
            float2 m00, m01, m10, m11;
            rot_mat(p[base + 0], p[base + 1], p[base + 2], m00, m01, m10, m11);
            const int sc = 8 >> q;
            const int st = 8 >> t;
            #pragma unroll
            for (int i = 0; i < 16; i++) {
                if (!(i & sc) || (i & st)) continue;  // control=1, target bit=0
                gate_pair(s[i], s[i + st], m00, m01, m10, m11);
            }
        }
    }
}

__device__ __forceinline__ void load_params48(const float* __restrict__ g, float p[48]) {
    const float4* g4 = reinterpret_cast<const float4*>(g);
    #pragma unroll
    for (int i = 0; i < 12; i++) {
        float4 v = __ldg(g4 + i);
        p[i * 4 + 0] = v.x; p[i * 4 + 1] = v.y;
        p[i * 4 + 2] = v.z; p[i * 4 + 3] = v.w;
    }
}

// ---------------------------------------------------------------------------
// Fused prep kernel: entities | relations | histogram, split by blockIdx.
// ---------------------------------------------------------------------------
#define HIST_BLOCKS 64

__global__ void prep_kernel(const float* __restrict__ ep, int E, int EB,
                            const float* __restrict__ rp, int R, int RB,
                            const int* __restrict__ r, int B) {
    __shared__ int sh[NR_MAX];

    if (blockIdx.x < EB) {
        int e = blockIdx.x * blockDim.x + threadIdx.x;
        if (e >= E) return;
        float p[48];
        load_params48(ep + (size_t)e * 48, p);
        float2 s[16];
        #pragma unroll
        for (int i = 0; i < 16; i++) s[i] = make_float2(0.25f, 0.0f);
        apply_block(s, p);
        float4* dst = reinterpret_cast<float4*>(g_ve + e * 16);
        #pragma unroll
        for (int i = 0; i < 8; i++)
            dst[i] = make_float4(s[2 * i].x, s[2 * i].y, s[2 * i + 1].x, s[2 * i + 1].y);
    } else if (blockIdx.x < EB + RB) {
        int idx = (blockIdx.x - EB) * blockDim.x + threadIdx.x;
        int rr = idx >> 4;
        int col = idx & 15;
        if (rr >= R) return;
        float p[48];
        load_params48(rp + (size_t)rr * 48, p);
        float2 s[16];
        #pragma unroll
        for (int i = 0; i < 16; i++) s[i] = make_float2(0.0f, 0.0f);
        s[col] = make_float2(1.0f, 0.0f);
        apply_block(s, p);
        #pragma unroll
        for (int i = 0; i < 16; i++)
            g_mr[rr * 256 + i * 16 + col] = s[i];
    } else {
        int hb = blockIdx.x - EB - RB;
        for (int i = threadIdx.x; i < NR_MAX; i += blockDim.x) sh[i] = 0;
        __syncthreads();
        int chunk = (B + HIST_BLOCKS - 1) / HIST_BLOCKS;
        int start = hb * chunk;
        int end = min(start + chunk, B);
        for (int b = start + threadIdx.x; b < end; b += blockDim.x)
            atomicAdd(&sh[r[b]], 1);
        __syncthreads();
        for (int i = threadIdx.x; i < NR_MAX; i += blockDim.x) {
            int c = sh[i];
            if (c) atomicAdd(&g_hist[i], c);
        }
    }
}

// ---------------------------------------------------------------------------
// Exclusive scan g_hist -> g_cursor; re-zero g_hist (graph-replay invariant).
// ---------------------------------------------------------------------------
__global__ void scan_kernel(int R) {
    __shared__ int warp_sums[32];
    int t = threadIdx.x;
    int v = (t < R) ? g_hist[t] : 0;
    int x = v;
    #pragma unroll
    for (int d = 1; d < 32; d <<= 1) {
        int y = __shfl_up_sync(0xffffffffu, x, d);
        if ((t & 31) >= d) x += y;
    }
    if ((t & 31) == 31) warp_sums[t >> 5] = x;
    __syncthreads();
    if (t < 32) {
        int s = warp_sums[t];
        #pragma unroll
        for (int d = 1; d < 32; d <<= 1) {
            int y = __shfl_up_sync(0xffffffffu, s, d);
            if (t >= d) s += y;
        }
        warp_sums[t] = s;
    }
    __syncthreads();
    int base = (t >= 32) ? warp_sums[(t >> 5) - 1] : 0;
    if (t < R) {
        g_cursor[t] = base + x - v;
        g_hist[t] = 0;
    }
}

// ---------------------------------------------------------------------------
// Block-aggregated scatter. Writes {b, h[b], r[b], t[b]} so score has zero
// scattered reads (one scattered STG.128 here instead).
// ---------------------------------------------------------------------------
#define SCAT_BLOCKS 64

__global__ void scatter_kernel(const int* __restrict__ h, const int* __restrict__ r,
                               const int* __restrict__ t, int B) {
    __shared__ int cnt[NR_MAX];
    __shared__ int base[NR_MAX];
    for (int i = threadIdx.x; i < NR_MAX; i += blockDim.x) cnt[i] = 0;
    __syncthreads();

    int chunk = (B + SCAT_BLOCKS - 1) / SCAT_BLOCKS;
    int start = blockIdx.x * chunk;
    int end = min(start + chunk, B);

    for (int b = start + threadIdx.x; b < end; b += blockDim.x)
        atomicAdd(&cnt[r[b]], 1);
    __syncthreads();

    for (int i = threadIdx.x; i < NR_MAX; i += blockDim.x) {
        int c = cnt[i];
        base[i] = c ? atomicAdd(&g_cursor[i], c) : 0;
        cnt[i] = 0;
    }
    __syncthreads();

    for (int b = start + threadIdx.x; b < end; b += blockDim.x) {
        int rr = r[b];
        int pos = base[rr] + atomicAdd(&cnt[rr], 1);
        g_pack[pos] = make_int4(b, h[b], rr, t[b]);
    }
}

// ---------------------------------------------------------------------------
// Score: score_b = Re( v_t^dagger * M_r * v_h ), relation-grouped order.
// 4 threads per item, each computing 4 rows of u = M*vh. s = tid>>6 is
// warp-uniform so M loads are broadcasts; items within a warp are consecutive
// in sorted order (r warp-uniform except at rare boundaries).
// ---------------------------------------------------------------------------
#define SC_ITEMS 64            // items per block
#define SC_THREADS 256         // 4 threads per item

__global__ void __launch_bounds__(SC_THREADS) score_kernel(float* __restrict__ out, int B) {
    __shared__ float4 sv_h[SC_ITEMS * 8];   // 4 KB, (chunk+item)&7 swizzle
    __shared__ float4 sv_t[SC_ITEMS * 8];   // 4 KB
    __shared__ int sh_h[SC_ITEMS];
    __shared__ int sh_t[SC_ITEMS];
    __shared__ int sh_r[SC_ITEMS];
    __shared__ int sh_b[SC_ITEMS];
    __shared__ float sred[SC_THREADS];      // 4-way partial sums

    const int tid = threadIdx.x;
    const int start = blockIdx.x * SC_ITEMS;

    if (tid < SC_ITEMS) {
        int idx = start + tid;
        if (idx < B) {
            int4 pk = __ldg(&g_pack[idx]);  // coalesced {b, h, r, t}
            sh_b[tid] = pk.x; sh_h[tid] = pk.y;
            sh_r[tid] = pk.z; sh_t[tid] = pk.w;
        } else {
            sh_b[tid] = -1; sh_h[tid] = 0; sh_r[tid] = 0; sh_t[tid] = 0;
        }
    }
    __syncthreads();

    // Cooperative staging: 64 items x 8 chunks = 512 float4 per vector.
    // 256 threads -> 2 rounds, each thread loads one h-chunk and one t-chunk.
    const float4* ve4 = reinterpret_cast<const float4*>(g_ve);
    #pragma unroll
    for (int p = 0; p < 2; p++) {
        int i = p * SC_THREADS + tid;       // 0..511
        int item = i >> 3;
        int chunk = i & 7;
        int sw = item * 8 + ((chunk + item) & 7);
        sv_h[sw] = __ldg(ve4 + (size_t)sh_h[item] * 8 + chunk);
        sv_t[sw] = __ldg(ve4 + (size_t)sh_t[item] * 8 + chunk);
    }
    __syncthreads();

    const int s = tid >> 6;        // row-slice 0..3 (warp-uniform)
    const int item = tid & 63;     // item within block

    // Full vh into registers (swizzled conflict-free LDS.128; 4 threads of an
    // item hit the same address -> smem broadcast).
    float2 vh[16];
    #pragma unroll
    for (int j = 0; j < 8; j++) {
        float4 a = sv_h[item * 8 + ((j + item) & 7)];
        vh[2 * j]     = make_float2(a.x, a.y);
        vh[2 * j + 1] = make_float2(a.z, a.w);
    }
    // This slice's 4 vt entries (chunks 2s, 2s+1).
    float2 vt[4];
    #pragma unroll
    for (int c = 0; c < 2; c++) {
        float4 v = sv_t[item * 8 + ((2 * s + c + item) & 7)];
        vt[2 * c]     = make_float2(v.x, v.y);
        vt[2 * c + 1] = make_float2(v.z, v.w);
    }

    // 4 rows of u = M * vh; accumulate Re(conj(vt_i) * u_i).
    const float4* M4 = reinterpret_cast<const float4*>(g_mr) + (size_t)sh_r[item] * 128 + s * 32;
    float acc = 0.0f;
    #pragma unroll
    for (int ir = 0; ir < 4; ir++) {
        float2 u = make_float2(0.0f, 0.0f);
        #pragma unroll
        for (int j4 = 0; j4 < 8; j4++) {
            float4 mm = __ldg(M4 + ir * 8 + j4);
            float2 a0 = vh[2 * j4];
            float2 a1 = vh[2 * j4 + 1];
            u.x += mm.x * a0.x - mm.y * a0.y + mm.z * a1.x - mm.w * a1.y;
            u.y += mm.x * a0.y + mm.y * a0.x + mm.z * a1.y + mm.w * a1.x;
        }
        acc += vt[ir].x * u.x + vt[ir].y * u.y;
    }
    sred[s * SC_ITEMS + item] = acc;
    __syncthreads();

    if (tid < SC_ITEMS) {
        int b = sh_b[tid];
        if (b >= 0) {
            out[b] = sred[tid] + sred[SC_ITEMS + tid] +
                     sred[2 * SC_ITEMS + tid] + sred[3 * SC_ITEMS + tid];
        }
    }
}

// ---------------------------------------------------------------------------
// Launch: prep -> scan -> scatter -> score.
// ---------------------------------------------------------------------------
extern "C" void kernel_launch(void* const* d_in, const int* in_sizes, int n_in,
                              void* d_out, int out_size) {
    const float* ep = (const float*)d_in[0];  // entity_params   [E,4,4,3]
    const float* rp = (const float*)d_in[1];  // relation_params [R,4,4,3]
    const int* h = (const int*)d_in[2];
    const int* r = (const int*)d_in[3];
    const int* t = (const int*)d_in[4];
    float* out = (float*)d_out;

    int E = in_sizes[0] / 48;
    int R = in_sizes[1] / 48;
    int B = in_sizes[2];

    int EB = (E + 255) / 256;
    int RB = (R * 16 + 255) / 256;

    prep_kernel<<<EB + RB + HIST_BLOCKS, 256>>>(ep, E, EB, rp, R, RB, r, B);
    scan_kernel<<<1, 1024>>>(R);
    scatter_kernel<<<SCAT_BLOCKS, 256>>>(h, r, t, B);
    score_kernel<<<(B + SC_ITEMS - 1) / SC_ITEMS, SC_THREADS>>>(out, B);
}